// round 8
// baseline (speedup 1.0000x reference)
#include <cuda_runtime.h>
#include <cuda_bf16.h>
#include <math.h>
#include <cstdint>

#define BB 8
#define LT 64
#define LV 16384
#define DD 256
#define EPSF 1e-6f

typedef unsigned int uint32;

#define PK 136   // padded row stride in bf16 elems per 128-K phase (272B; 68 words % 32 == 4 -> conflict-free)

// smem byte offsets (per 128-K phase tiles)
#define SM_VH   0
#define SM_VL   34816
#define SM_TH   69632
#define SM_TL   87040
#define SM_RN   104448
#define SM_RED  104960
#define SM_TOTAL 111104

// ---------------- device globals ----------------
__device__ unsigned short g_th[BB*LT*DD];   // bf16 hi of normalized t
__device__ unsigned short g_tl[BB*LT*DD];   // bf16 lo
__device__ float g_ES[(size_t)BB*LV*LT];    // exp(S), fp32
__device__ float g_den[BB*LT];
__device__ float g_num[BB*LT];
__device__ float g_zc[BB*LT];
__device__ float g_w[BB*LT];
__device__ unsigned g_mn[BB];
__device__ unsigned g_mx[BB];

__device__ __forceinline__ float fixf(float x) {
    if (isnan(x)) return 0.f;
    return fminf(fmaxf(x, -3.402823466e38f), 3.402823466e38f);
}
__device__ __forceinline__ uint32 smem_u32(const void* p) {
    uint32 a;
    asm("{ .reg .u64 t; cvta.to.shared.u64 t, %1; cvt.u32.u64 %0, t; }" : "=r"(a) : "l"(p));
    return a;
}
__device__ __forceinline__ uint32 pack2(float a, float b) {
    __nv_bfloat162 h = __floats2bfloat162_rn(a, b);
    return *(uint32*)&h;
}

#define LDMX4(r, addr) \
    asm volatile("ldmatrix.sync.aligned.m8n8.x4.shared.b16 {%0,%1,%2,%3}, [%4];" \
        : "=r"((r)[0]), "=r"((r)[1]), "=r"((r)[2]), "=r"((r)[3]) : "r"(addr))

#define MMA(c, a, b0, b1) \
    asm volatile("mma.sync.aligned.m16n8k16.row.col.f32.bf16.bf16.f32 " \
        "{%0,%1,%2,%3},{%4,%5,%6,%7},{%8,%9},{%0,%1,%2,%3};" \
        : "+f"((c)[0]), "+f"((c)[1]), "+f"((c)[2]), "+f"((c)[3]) \
        : "r"((a)[0]), "r"((a)[1]), "r"((a)[2]), "r"((a)[3]), "r"(b0), "r"(b1))

// ---------------- kernel 1: normalize t -> bf16 hi/lo; init accumulators ----------------
__global__ void k1_norm_t(const float* __restrict__ t) {
    int row = blockIdx.x;         // 0..511
    int tid = threadIdx.x;        // 0..255 = k
    if (row == 0) {
        for (int j = tid; j < BB*LT; j += 256) {
            g_den[j] = 0.f; g_num[j] = 0.f; g_zc[j] = 0.f;
        }
        if (tid < BB) { g_mn[tid] = 0x7F800000u; g_mx[tid] = 0u; }
    }
    float x = fixf(t[row*DD + tid]);
    float ss = x * x;
    #pragma unroll
    for (int o = 16; o >= 1; o >>= 1) ss += __shfl_xor_sync(0xffffffffu, ss, o);
    __shared__ float sh[8];
    if ((tid & 31) == 0) sh[tid >> 5] = ss;
    __syncthreads();
    float tot = 0.f;
    #pragma unroll
    for (int w = 0; w < 8; w++) tot += sh[w];
    float xn = x / fmaxf(sqrtf(tot), EPSF);
    __nv_bfloat16 hi = __float2bfloat16(xn);
    __nv_bfloat16 lo = __float2bfloat16(xn - __bfloat162float(hi));
    g_th[row*DD + tid] = *(unsigned short*)&hi;
    g_tl[row*DD + tid] = *(unsigned short*)&lo;
}

// ---------------- kernel 2: HMMA bf16-split S-GEMM, K-split 2-phase, 2 CTAs/SM ----------------
// Block: 128 v-rows x 64 t; K processed in two 128-halves. 8 warps; warp w owns rows 16w..16w+15.
__global__ __launch_bounds__(256, 2) void k2_main(const float* __restrict__ v) {
    extern __shared__ char smc[];
    uint32 smb = smem_u32(smc);
    int b    = blockIdx.y;
    int row0 = blockIdx.x * 128;
    int tid  = threadIdx.x;
    int lane = tid & 31, w = tid >> 5;
    float* rn_s = (float*)(smc + SM_RN);
    float* red  = (float*)(smc + SM_RED);

    float acc[8][4];
    #pragma unroll
    for (int nt = 0; nt < 8; nt++)
        #pragma unroll
        for (int j = 0; j < 4; j++) acc[nt][j] = 0.f;

    // ldmatrix addresses (phase-independent; smem reloaded per phase)
    uint32 a_row = 16*w + (lane & 15);
    uint32 a_k8  = (lane >> 4) * 8;
    uint32 ah_addr = smb + SM_VH + (a_row*PK + a_k8) * 2;
    uint32 al_addr = smb + SM_VL + (a_row*PK + a_k8) * 2;
    uint32 b_row = (lane & 7) + ((lane >> 4) << 3);
    uint32 b_k8  = ((lane >> 3) & 1) * 8;
    uint32 b_base = (b_row*PK + b_k8) * 2;

    int vrow = tid >> 1, khalf = (tid & 1) * 64;
    float ss = 0.f;

    #pragma unroll
    for (int ph = 0; ph < 2; ph++) {
        if (ph) __syncthreads();   // all warps done reading previous phase tiles

        // ---- load T half (bf16 hi/lo) into padded smem ----
        {
            const uint4* th4 = (const uint4*)(g_th + b*LT*DD + ph*128);
            const uint4* tl4 = (const uint4*)(g_tl + b*LT*DD + ph*128);
            #pragma unroll
            for (int it = 0; it < 4; it++) {
                int i = tid + it*256;            // 0..1023
                int r = i >> 4, c = i & 15;      // 16 uint4 per 128-elem row
                uint32 off = (uint32)(r*PK + c*8) * 2;
                // global row stride = DD/8 = 32 uint4
                *(uint4*)(smc + SM_TH + off) = th4[r*32 + c];
                *(uint4*)(smc + SM_TL + off) = tl4[r*32 + c];
            }
        }
        // ---- load + split V half ----
        {
            const float* vr = v + ((size_t)b*LV + row0 + vrow)*DD + ph*128 + khalf;
            #pragma unroll
            for (int c = 0; c < 8; c++) {
                float4 p0 = *(const float4*)(vr + c*8);
                float4 p1 = *(const float4*)(vr + c*8 + 4);
                float x[8];
                x[0]=fixf(p0.x); x[1]=fixf(p0.y); x[2]=fixf(p0.z); x[3]=fixf(p0.w);
                x[4]=fixf(p1.x); x[5]=fixf(p1.y); x[6]=fixf(p1.z); x[7]=fixf(p1.w);
                uint32 hi[4], lo[4];
                #pragma unroll
                for (int j = 0; j < 4; j++) {
                    float a = x[2*j], bb2 = x[2*j+1];
                    ss += a*a + bb2*bb2;
                    __nv_bfloat16 ha = __float2bfloat16(a), hb = __float2bfloat16(bb2);
                    float la = a - __bfloat162float(ha), lb = bb2 - __bfloat162float(hb);
                    hi[j] = (uint32)(*(unsigned short*)&ha) | ((uint32)(*(unsigned short*)&hb) << 16);
                    lo[j] = pack2(la, lb);
                }
                uint32 off = (uint32)(vrow*PK + khalf + c*8) * 2;
                *(uint4*)(smc + SM_VH + off) = make_uint4(hi[0], hi[1], hi[2], hi[3]);
                *(uint4*)(smc + SM_VL + off) = make_uint4(lo[0], lo[1], lo[2], lo[3]);
            }
            if (ph == 1) {
                float st = ss + __shfl_xor_sync(0xffffffffu, ss, 1);
                if ((tid & 1) == 0) rn_s[vrow] = 0.5f / fmaxf(sqrtf(st), EPSF);
            }
        }
        __syncthreads();

        // ---- MMA over this K-half: 8 k-steps x 3 passes ----
        #pragma unroll 2
        for (int ks = 0; ks < 8; ks++) {
            uint32 ah[4], al[4];
            LDMX4(ah, ah_addr + ks*32);
            LDMX4(al, al_addr + ks*32);
            #pragma unroll
            for (int nc = 0; nc < 4; nc++) {
                uint32 boff = b_base + (uint32)nc*(16*PK*2) + ks*32;
                uint32 bh[4], bl[4];
                LDMX4(bh, smb + SM_TH + boff);
                LDMX4(bl, smb + SM_TL + boff);
                MMA(acc[2*nc],   ah, bh[0], bh[1]);
                MMA(acc[2*nc+1], ah, bh[2], bh[3]);
                MMA(acc[2*nc],   al, bh[0], bh[1]);
                MMA(acc[2*nc+1], al, bh[2], bh[3]);
                MMA(acc[2*nc],   ah, bl[0], bl[1]);
                MMA(acc[2*nc+1], ah, bl[2], bl[3]);
            }
        }
    }

    // ---- epilogue: shift-free softmax over t (|S|<=0.5), ES store, accumulators ----
    // c frag: row r1 = 16w + lane/4 -> c[0],c[1]; row r2 = r1+8 -> c[2],c[3];
    // col = nt*8 + (lane&3)*2 + e
    int r1 = 16*w + (lane >> 2);
    int r2 = r1 + 8;
    float sc1 = rn_s[r1], sc2 = rn_s[r2];

    float e1[16], e2[16];
    float z1 = 0.f, z2 = 0.f;
    #pragma unroll
    for (int nt = 0; nt < 8; nt++) {
        e1[2*nt]   = __expf(acc[nt][0]*sc1); z1 += e1[2*nt];
        e1[2*nt+1] = __expf(acc[nt][1]*sc1); z1 += e1[2*nt+1];
        e2[2*nt]   = __expf(acc[nt][2]*sc2); z2 += e2[2*nt];
        e2[2*nt+1] = __expf(acc[nt][3]*sc2); z2 += e2[2*nt+1];
    }
    #pragma unroll
    for (int o = 1; o < 4; o <<= 1) {
        z1 += __shfl_xor_sync(0xffffffffu, z1, o);
        z2 += __shfl_xor_sync(0xffffffffu, z2, o);
    }
    float iz1 = 1.f / z1, iz2 = 1.f / z2;

    float dp[16], np[16], zp[16];
    {
        float2* es1p = (float2*)&g_ES[((size_t)b*LV + row0 + r1)*LT] + (lane & 3);
        float2* es2p = (float2*)&g_ES[((size_t)b*LV + row0 + r2)*LT] + (lane & 3);
        #pragma unroll
        for (int nt = 0; nt < 8; nt++) {
            float es1a = e1[2*nt], es1b = e1[2*nt+1];   // exp(S)
            float es2a = e2[2*nt], es2b = e2[2*nt+1];
            es1p[nt*4] = make_float2(es1a, es1b);
            es2p[nt*4] = make_float2(es2a, es2b);
            float a1a = es1a*iz1, a1b = es1b*iz1;       // A_vt
            float a2a = es2a*iz2, a2b = es2b*iz2;
            float w1a = __expf(a1a*0.5f), w1b = __expf(a1b*0.5f);
            float w2a = __expf(a2a*0.5f), w2b = __expf(a2b*0.5f);
            dp[2*nt]   = w1a + w2a;         dp[2*nt+1] = w1b + w2b;
            np[2*nt]   = w1a*a1a + w2a*a2a; np[2*nt+1] = w1b*a1b + w2b*a2b;
            zp[2*nt]   = es1a + es2a;       zp[2*nt+1] = es1b + es2b;
        }
    }
    // reduce across the 8 row-groups in the warp (lane bits 2,3,4)
    #pragma unroll
    for (int o = 4; o <= 16; o <<= 1) {
        #pragma unroll
        for (int i = 0; i < 16; i++) {
            dp[i] += __shfl_xor_sync(0xffffffffu, dp[i], o);
            np[i] += __shfl_xor_sync(0xffffffffu, np[i], o);
            zp[i] += __shfl_xor_sync(0xffffffffu, zp[i], o);
        }
    }
    if (lane < 4) {
        #pragma unroll
        for (int nt = 0; nt < 8; nt++) {
            int col = nt*8 + lane*2;
            red[w*192 +       col] = dp[2*nt];  red[w*192 +       col+1] = dp[2*nt+1];
            red[w*192 +  64 + col] = np[2*nt];  red[w*192 +  64 + col+1] = np[2*nt+1];
            red[w*192 + 128 + col] = zp[2*nt];  red[w*192 + 128 + col+1] = zp[2*nt+1];
        }
    }
    __syncthreads();
    if (tid < 192) {
        float s = 0.f;
        #pragma unroll
        for (int y = 0; y < 8; y++) s += red[y*192 + tid];
        int which = tid >> 6, t = tid & 63;
        float* dst = (which == 0) ? g_den : ((which == 1) ? g_num : g_zc);
        atomicAdd(&dst[b*LT + t], s);
    }
}

// ---------------- kernel 3: text_score -> w = ts / Zc ----------------
__global__ void k3_ts() {
    int b = blockIdx.x, t = threadIdx.x;
    int i = b*LT + t;
    float ts = g_num[i] / g_den[i];
    float s = ts;
    #pragma unroll
    for (int o = 16; o >= 1; o >>= 1) s += __shfl_xor_sync(0xffffffffu, s, o);
    __shared__ float sh[2];
    if ((t & 31) == 0) sh[t >> 5] = s;
    __syncthreads();
    float tot = sh[0] + sh[1];
    ts = ts / (tot + EPSF);
    g_w[i] = ts / g_zc[i];
}

// ---------------- kernel 4: scores = ES . w, plus min/max ----------------
__global__ __launch_bounds__(256) void k4_score(float* __restrict__ out) {
    int b   = blockIdx.y;
    int tid = threadIdx.x;
    __shared__ float w_s[LT];
    __shared__ float sc_s[32];
    if (tid < LT) w_s[tid] = g_w[b*LT + tid];
    __syncthreads();
    int r  = blockIdx.x*32 + (tid >> 3);
    int l8 = tid & 7;
    const float* e = g_ES + ((size_t)b*LV + r)*LT + l8*8;
    float4 e0 = *(const float4*)e;
    float4 e1 = *(const float4*)(e + 4);
    const float* w = w_s + l8*8;
    float s = e0.x*w[0] + e0.y*w[1] + e0.z*w[2] + e0.w*w[3]
            + e1.x*w[4] + e1.y*w[5] + e1.z*w[6] + e1.w*w[7];
    s += __shfl_xor_sync(0xffffffffu, s, 1);
    s += __shfl_xor_sync(0xffffffffu, s, 2);
    s += __shfl_xor_sync(0xffffffffu, s, 4);
    if (l8 == 0) { out[(size_t)b*LV + r] = s; sc_s[tid >> 3] = s; }
    __syncthreads();
    if (tid == 0) {
        float mn = sc_s[0], mx = sc_s[0];
        #pragma unroll
        for (int i = 1; i < 32; i++) { mn = fminf(mn, sc_s[i]); mx = fmaxf(mx, sc_s[i]); }
        atomicMin(&g_mn[b], __float_as_uint(mn));   // scores > 0: uint order == float order
        atomicMax(&g_mx[b], __float_as_uint(mx));
    }
}

// ---------------- kernel 5: min-max rescale ----------------
__global__ void k5_final(float* __restrict__ out) {
    int idx = blockIdx.x*256 + threadIdx.x;
    int b = idx >> 14;
    float mn = __uint_as_float(g_mn[b]);
    float mx = __uint_as_float(g_mx[b]);
    out[idx] = (out[idx] - mn) / (mx - mn + EPSF);
}

extern "C" void kernel_launch(void* const* d_in, const int* in_sizes, int n_in,
                              void* d_out, int out_size) {
    const float* t = (const float*)d_in[0];
    const float* v = (const float*)d_in[1];
    if (in_sizes[0] != BB*LT*DD) { const float* tmp = t; t = v; v = tmp; }

    cudaFuncSetAttribute(k2_main, cudaFuncAttributeMaxDynamicSharedMemorySize, SM_TOTAL);

    k1_norm_t<<<BB*LT, 256>>>(t);
    k2_main<<<dim3(LV/128, BB), 256, SM_TOTAL>>>(v);
    k3_ts<<<BB, 64>>>();
    k4_score<<<dim3(LV/32, BB), 256>>>((float*)d_out);
    k5_final<<<(BB*LV)/256, 256>>>((float*)d_out);
}

// round 9
// speedup vs baseline: 1.4843x; 1.4843x over previous
#include <cuda_runtime.h>
#include <cuda_fp16.h>
#include <math.h>
#include <cstdint>

#define BB 8
#define LT 64
#define LV 16384
#define DD 256
#define EPSF 1e-6f

typedef unsigned int uint32;

#define PK 264   // padded row stride in fp16 elems (528B; 33 uint4 -> odd 16B-unit stride, conflict-free ldmatrix)

// smem byte offsets
#define SM_V    0                      // 128*264*2 = 67584
#define SM_T    67584                  // 64*264*2  = 33792
#define SM_RN   101376                 // 512
#define SM_RED  101888                 // 8*192*4 = 6144
#define SM_TOTAL 108032                // x2 CTAs = 216064 <= 227 KB

// ---------------- device globals ----------------
__device__ __half g_t16[BB*LT*DD];    // fp16 normalized t
__device__ float g_ES[(size_t)BB*LV*LT];
__device__ float g_den[BB*LT];
__device__ float g_num[BB*LT];
__device__ float g_zc[BB*LT];
__device__ float g_w[BB*LT];
__device__ unsigned g_mn[BB];
__device__ unsigned g_mx[BB];

__device__ __forceinline__ float fixf(float x) {
    if (isnan(x)) return 0.f;
    return fminf(fmaxf(x, -3.402823466e38f), 3.402823466e38f);
}
__device__ __forceinline__ uint32 smem_u32(const void* p) {
    uint32 a;
    asm("{ .reg .u64 t; cvta.to.shared.u64 t, %1; cvt.u32.u64 %0, t; }" : "=r"(a) : "l"(p));
    return a;
}
__device__ __forceinline__ uint32 packh2(float a, float b) {
    __half2 h = __floats2half2_rn(a, b);
    return *(uint32*)&h;
}

#define LDMX4(r, addr) \
    asm volatile("ldmatrix.sync.aligned.m8n8.x4.shared.b16 {%0,%1,%2,%3}, [%4];" \
        : "=r"((r)[0]), "=r"((r)[1]), "=r"((r)[2]), "=r"((r)[3]) : "r"(addr))

#define MMAH(c, a, b0, b1) \
    asm volatile("mma.sync.aligned.m16n8k16.row.col.f32.f16.f16.f32 " \
        "{%0,%1,%2,%3},{%4,%5,%6,%7},{%8,%9},{%0,%1,%2,%3};" \
        : "+f"((c)[0]), "+f"((c)[1]), "+f"((c)[2]), "+f"((c)[3]) \
        : "r"((a)[0]), "r"((a)[1]), "r"((a)[2]), "r"((a)[3]), "r"(b0), "r"(b1))

// ---------------- kernel 1: normalize t -> fp16; init accumulators ----------------
__global__ void k1_norm_t(const float* __restrict__ t) {
    int row = blockIdx.x;         // 0..511
    int tid = threadIdx.x;        // 0..255 = k
    if (row == 0) {
        for (int j = tid; j < BB*LT; j += 256) {
            g_den[j] = 0.f; g_num[j] = 0.f; g_zc[j] = 0.f;
        }
        if (tid < BB) { g_mn[tid] = 0x7F800000u; g_mx[tid] = 0u; }
    }
    float x = fixf(t[row*DD + tid]);
    float ss = x * x;
    #pragma unroll
    for (int o = 16; o >= 1; o >>= 1) ss += __shfl_xor_sync(0xffffffffu, ss, o);
    __shared__ float sh[8];
    if ((tid & 31) == 0) sh[tid >> 5] = ss;
    __syncthreads();
    float tot = 0.f;
    #pragma unroll
    for (int w = 0; w < 8; w++) tot += sh[w];
    float xn = x / fmaxf(sqrtf(tot), EPSF);
    g_t16[row*DD + tid] = __float2half_rn(xn);
}

// ---------------- kernel 2: single-pass fp16 HMMA S-GEMM + fused softmaxes ----------------
// Block: 128 v-rows x 64 t x K=256, single phase. 8 warps; warp w owns rows 16w..16w+15.
__global__ __launch_bounds__(256, 2) void k2_main(const float* __restrict__ v) {
    extern __shared__ char smc[];
    uint32 smb = smem_u32(smc);
    int b    = blockIdx.y;
    int row0 = blockIdx.x * 128;
    int tid  = threadIdx.x;
    int lane = tid & 31, w = tid >> 5;
    float* rn_s = (float*)(smc + SM_RN);
    float* red  = (float*)(smc + SM_RED);

    // ---- prologue: T fp16 tile into padded smem (2048 uint4) ----
    {
        const uint4* t4 = (const uint4*)(g_t16 + b*LT*DD);
        #pragma unroll
        for (int it = 0; it < 8; it++) {
            int i = tid + it*256;            // 0..2047
            int r = i >> 5, c = i & 31;      // 32 uint4 per 256-elem row
            *(uint4*)(smc + SM_T + (uint32)(r*PK + c*8)*2) = t4[i];
        }
    }
    // ---- prologue: V -> fp16 + row norms ----
    {
        int vrow = tid >> 1, khalf = (tid & 1) * 128;
        const float* vr = v + ((size_t)b*LV + row0 + vrow)*DD + khalf;
        float ss = 0.f;
        #pragma unroll 4
        for (int c = 0; c < 16; c++) {
            float4 p0 = *(const float4*)(vr + c*8);
            float4 p1 = *(const float4*)(vr + c*8 + 4);
            float x0=fixf(p0.x), x1=fixf(p0.y), x2=fixf(p0.z), x3=fixf(p0.w);
            float x4=fixf(p1.x), x5=fixf(p1.y), x6=fixf(p1.z), x7=fixf(p1.w);
            ss += x0*x0 + x1*x1 + x2*x2 + x3*x3 + x4*x4 + x5*x5 + x6*x6 + x7*x7;
            uint4 st = make_uint4(packh2(x0,x1), packh2(x2,x3), packh2(x4,x5), packh2(x6,x7));
            *(uint4*)(smc + SM_V + (uint32)(vrow*PK + khalf + c*8)*2) = st;
        }
        float st = ss + __shfl_xor_sync(0xffffffffu, ss, 1);
        if ((tid & 1) == 0) rn_s[vrow] = 0.5f / fmaxf(sqrtf(st), EPSF);
    }
    __syncthreads();

    // ---- mainloop: 16 k-steps, single fp16 pass ----
    float acc[8][4];
    #pragma unroll
    for (int nt = 0; nt < 8; nt++)
        #pragma unroll
        for (int j = 0; j < 4; j++) acc[nt][j] = 0.f;

    uint32 a_row = 16*w + (lane & 15);
    uint32 a_k8  = (lane >> 4) * 8;
    uint32 a_addr = smb + SM_V + (a_row*PK + a_k8) * 2;
    uint32 b_row = (lane & 7) + ((lane >> 4) << 3);
    uint32 b_k8  = ((lane >> 3) & 1) * 8;
    uint32 b_base = smb + SM_T + (b_row*PK + b_k8) * 2;

    #pragma unroll 4
    for (int ks = 0; ks < 16; ks++) {
        uint32 a[4];
        LDMX4(a, a_addr + ks*32);
        #pragma unroll
        for (int nc = 0; nc < 4; nc++) {
            uint32 bh[4];
            LDMX4(bh, b_base + (uint32)nc*(16*PK*2) + ks*32);
            MMAH(acc[2*nc],   a, bh[0], bh[1]);
            MMAH(acc[2*nc+1], a, bh[2], bh[3]);
        }
    }

    // ---- epilogue: shift-free softmax over t (|S|<=0.5), ES store, accumulators ----
    // c frag: row r1 = 16w + lane/4 -> c[0],c[1]; row r2 = r1+8 -> c[2],c[3];
    // col = nt*8 + (lane&3)*2 + e
    int r1 = 16*w + (lane >> 2);
    int r2 = r1 + 8;
    float sc1 = rn_s[r1], sc2 = rn_s[r2];

    // exp in place; z = row sums
    float z1 = 0.f, z2 = 0.f;
    #pragma unroll
    for (int nt = 0; nt < 8; nt++) {
        acc[nt][0] = __expf(acc[nt][0]*sc1); z1 += acc[nt][0];
        acc[nt][1] = __expf(acc[nt][1]*sc1); z1 += acc[nt][1];
        acc[nt][2] = __expf(acc[nt][2]*sc2); z2 += acc[nt][2];
        acc[nt][3] = __expf(acc[nt][3]*sc2); z2 += acc[nt][3];
    }
    #pragma unroll
    for (int o = 1; o < 4; o <<= 1) {
        z1 += __shfl_xor_sync(0xffffffffu, z1, o);
        z2 += __shfl_xor_sync(0xffffffffu, z2, o);
    }
    float iz1 = 1.f / z1, iz2 = 1.f / z2;

    float2* es1p = (float2*)&g_ES[((size_t)b*LV + row0 + r1)*LT] + (lane & 3);
    float2* es2p = (float2*)&g_ES[((size_t)b*LV + row0 + r2)*LT] + (lane & 3);
    #pragma unroll
    for (int nt = 0; nt < 8; nt++) {
        float es1a = acc[nt][0], es1b = acc[nt][1];   // exp(S) row1 (shift-free)
        float es2a = acc[nt][2], es2b = acc[nt][3];
        es1p[nt*4] = make_float2(es1a, es1b);
        es2p[nt*4] = make_float2(es2a, es2b);
        float a1a = es1a*iz1, a1b = es1b*iz1;          // A_vt
        float a2a = es2a*iz2, a2b = es2b*iz2;
        float w1a = __expf(a1a*0.5f), w1b = __expf(a1b*0.5f);
        float w2a = __expf(a2a*0.5f), w2b = __expf(a2b*0.5f);
        float dpa = w1a + w2a,          dpb = w1b + w2b;
        float npa = w1a*a1a + w2a*a2a,  npb = w1b*a1b + w2b*a2b;
        float zpa = es1a + es2a,        zpb = es1b + es2b;
        // reduce the 8 row-groups of the warp right away (6 live regs, not 48)
        #pragma unroll
        for (int o = 4; o <= 16; o <<= 1) {
            dpa += __shfl_xor_sync(0xffffffffu, dpa, o);
            dpb += __shfl_xor_sync(0xffffffffu, dpb, o);
            npa += __shfl_xor_sync(0xffffffffu, npa, o);
            npb += __shfl_xor_sync(0xffffffffu, npb, o);
            zpa += __shfl_xor_sync(0xffffffffu, zpa, o);
            zpb += __shfl_xor_sync(0xffffffffu, zpb, o);
        }
        if (lane < 4) {
            int col = nt*8 + lane*2;
            red[w*192 +       col] = dpa;  red[w*192 +       col+1] = dpb;
            red[w*192 +  64 + col] = npa;  red[w*192 +  64 + col+1] = npb;
            red[w*192 + 128 + col] = zpa;  red[w*192 + 128 + col+1] = zpb;
        }
    }
    __syncthreads();
    if (tid < 192) {
        float s = 0.f;
        #pragma unroll
        for (int y = 0; y < 8; y++) s += red[y*192 + tid];
        int which = tid >> 6, t = tid & 63;
        float* dst = (which == 0) ? g_den : ((which == 1) ? g_num : g_zc);
        atomicAdd(&dst[b*LT + t], s);
    }
}

// ---------------- kernel 3: text_score -> w = ts / Zc ----------------
__global__ void k3_ts() {
    int b = blockIdx.x, t = threadIdx.x;
    int i = b*LT + t;
    float ts = g_num[i] / g_den[i];
    float s = ts;
    #pragma unroll
    for (int o = 16; o >= 1; o >>= 1) s += __shfl_xor_sync(0xffffffffu, s, o);
    __shared__ float sh[2];
    if ((t & 31) == 0) sh[t >> 5] = s;
    __syncthreads();
    float tot = sh[0] + sh[1];
    ts = ts / (tot + EPSF);
    g_w[i] = ts / g_zc[i];
}

// ---------------- kernel 4: scores = ES . w, plus min/max ----------------
// 64 rows/block; thread handles one row-quarter: 16 cols = 4 back-to-back LDG.128.
__global__ __launch_bounds__(256) void k4_score(float* __restrict__ out) {
    int b   = blockIdx.y;
    int tid = threadIdx.x;
    __shared__ float w_s[LT];
    __shared__ float sc_s[64];
    if (tid < LT) w_s[tid] = g_w[b*LT + tid];
    __syncthreads();
    int r  = blockIdx.x*64 + (tid >> 2);
    int q  = tid & 3;                       // col quarter
    const float* e = g_ES + ((size_t)b*LV + r)*LT + q*16;
    float4 e0 = *(const float4*)e;
    float4 e1 = *(const float4*)(e + 4);
    float4 e2 = *(const float4*)(e + 8);
    float4 e3 = *(const float4*)(e + 12);
    const float* wq = w_s + q*16;
    float s = e0.x*wq[0]  + e0.y*wq[1]  + e0.z*wq[2]  + e0.w*wq[3]
            + e1.x*wq[4]  + e1.y*wq[5]  + e1.z*wq[6]  + e1.w*wq[7]
            + e2.x*wq[8]  + e2.y*wq[9]  + e2.z*wq[10] + e2.w*wq[11]
            + e3.x*wq[12] + e3.y*wq[13] + e3.z*wq[14] + e3.w*wq[15];
    s += __shfl_xor_sync(0xffffffffu, s, 1);
    s += __shfl_xor_sync(0xffffffffu, s, 2);
    if (q == 0) { out[(size_t)b*LV + r] = s; sc_s[tid >> 2] = s; }
    __syncthreads();
    if (tid == 0) {
        float mn = sc_s[0], mx = sc_s[0];
        #pragma unroll
        for (int i = 1; i < 64; i++) { mn = fminf(mn, sc_s[i]); mx = fmaxf(mx, sc_s[i]); }
        atomicMin(&g_mn[b], __float_as_uint(mn));   // scores > 0: uint order == float order
        atomicMax(&g_mx[b], __float_as_uint(mx));
    }
}

// ---------------- kernel 5: min-max rescale ----------------
__global__ void k5_final(float* __restrict__ out) {
    int idx = blockIdx.x*256 + threadIdx.x;
    int b = idx >> 14;
    float mn = __uint_as_float(g_mn[b]);
    float mx = __uint_as_float(g_mx[b]);
    out[idx] = (out[idx] - mn) / (mx - mn + EPSF);
}

extern "C" void kernel_launch(void* const* d_in, const int* in_sizes, int n_in,
                              void* d_out, int out_size) {
    const float* t = (const float*)d_in[0];
    const float* v = (const float*)d_in[1];
    if (in_sizes[0] != BB*LT*DD) { const float* tmp = t; t = v; v = tmp; }

    cudaFuncSetAttribute(k2_main, cudaFuncAttributeMaxDynamicSharedMemorySize, SM_TOTAL);

    k1_norm_t<<<BB*LT, 256>>>(t);
    k2_main<<<dim3(LV/128, BB), 256, SM_TOTAL>>>(v);
    k3_ts<<<BB, 64>>>();
    k4_score<<<dim3(LV/64, BB), 256>>>((float*)d_out);
    k5_final<<<(BB*LV)/256, 256>>>((float*)d_out);
}